// round 4
// baseline (speedup 1.0000x reference)
#include <cuda_runtime.h>

#define B_    16
#define L_    8192
#define CH_   32
#define NBLK  24
#define TILE  64
#define PSTR  68      // padded shared row stride (float4-aligned, low conflicts)
#define NTHR  256
#define PPW   8       // positions per thread (warp covers 8 positions x 32 channels)

// Scratch (device globals: allocation-free per harness rules)
__device__ float g_h0[B_*L_*CH_];
__device__ float g_h1[B_*L_*CH_];
__device__ float g_skip[B_*L_*CH_];
__device__ float g_pool[B_*128];

// ---------------------------------------------------------------------------
// Initial causal conv (K=2, dil=1): x (B,L) -> h (B,L,32); zero skip_sum.
// ---------------------------------------------------------------------------
__global__ void init_kernel(const float* __restrict__ x,
                            const float* __restrict__ W0,
                            const float* __restrict__ b0) {
    int idx = blockIdx.x * blockDim.x + threadIdx.x;
    if (idx >= B_*L_*CH_) return;
    int c = idx & 31;
    int l = (idx >> 5) & (L_ - 1);
    int b = idx >> 18;                       // /(L_*CH_) = /2^18
    float xv = x[b*L_ + l];
    float xp = (l > 0) ? x[b*L_ + l - 1] : 0.f;
    // conv taps: k=0 -> x[l-1], k=1 -> x[l]
    g_h0[idx] = fmaf(W0[c*2 + 0], xp, fmaf(W0[c*2 + 1], xv, b0[c]));
    g_skip[idx] = 0.f;
}

// ---------------------------------------------------------------------------
// One WaveNet residual block:
//   z = dilated causal conv (64 out ch, taps at l-dil and l)
//   gated = tanh(z[:32]) * sigmoid(z[32:])
//   skip  = W1 @ gated + b1
//   h_out = h_in + skip ; skip_sum += skip
// ---------------------------------------------------------------------------
__global__ __launch_bounds__(NTHR) void layer_kernel(
    const float* __restrict__ h_in, float* __restrict__ h_out,
    float* __restrict__ skip_sum,
    const float* __restrict__ Wd, const float* __restrict__ bd,
    const float* __restrict__ W1, const float* __restrict__ b1,
    int dil)
{
    __shared__ __align__(16) float wf0[32][32], wf1[32][32];   // [c][o]
    __shared__ __align__(16) float wg0[32][32], wg1[32][32];
    __shared__ __align__(16) float w1s[32][32];
    __shared__ float bdf[32], bdg[32], b1s[32];
    __shared__ __align__(16) float hTc[32][PSTR];              // [c][pos]
    __shared__ __align__(16) float hTp[32][PSTR];
    __shared__ __align__(16) float gT [32][PSTR];

    const int tid = threadIdx.x;
    const int b  = blockIdx.y;
    const int l0 = blockIdx.x * TILE;

    // ---- stage weights (Wd layout: [o][c][t], t=0 -> h[l-dil], t=1 -> h[l])
    for (int i = tid; i < 64*32*2; i += NTHR) {
        float v = Wd[i];
        int o = i >> 6;
        int c = (i >> 1) & 31;
        int t = i & 1;
        if (o < 32) { if (t) wf1[c][o]    = v; else wf0[c][o]    = v; }
        else        { if (t) wg1[c][o-32] = v; else wg0[c][o-32] = v; }
    }
    for (int i = tid; i < 1024; i += NTHR)
        w1s[i & 31][i >> 5] = W1[i];                 // w1s[c][o] = W1[o][c]
    if (tid < 32) { bdf[tid] = bd[tid]; bdg[tid] = bd[32 + tid]; b1s[tid] = b1[tid]; }

    // ---- stage h tile, transposed to [channel][position]
    const int base = (b*L_ + l0) * CH_;
    for (int i = tid; i < TILE*CH_; i += NTHR) {
        int l = i >> 5, c = i & 31;
        hTc[c][l] = h_in[base + i];
        int lp = l0 + l - dil;
        hTp[c][l] = (lp >= 0) ? h_in[(b*L_ + lp)*CH_ + c] : 0.f;   // causal zero pad
    }
    __syncthreads();

    const int w  = tid >> 5;       // warp -> 8-position group
    const int o  = tid & 31;       // lane -> output channel
    const int pb = w * PPW;

    float accf[PPW], accg[PPW];
    #pragma unroll
    for (int j = 0; j < PPW; j++) { accf[j] = bdf[o]; accg[j] = bdg[o]; }

    #pragma unroll 4
    for (int c = 0; c < 32; c++) {
        float a0 = wf0[c][o], a1 = wf1[c][o];
        float g0 = wg0[c][o], g1 = wg1[c][o];
        float4 hp0 = *(const float4*)&hTp[c][pb];
        float4 hp1 = *(const float4*)&hTp[c][pb + 4];
        float4 hc0 = *(const float4*)&hTc[c][pb];
        float4 hc1 = *(const float4*)&hTc[c][pb + 4];
        float hp[8] = {hp0.x,hp0.y,hp0.z,hp0.w, hp1.x,hp1.y,hp1.z,hp1.w};
        float hc[8] = {hc0.x,hc0.y,hc0.z,hc0.w, hc1.x,hc1.y,hc1.z,hc1.w};
        #pragma unroll
        for (int j = 0; j < PPW; j++) {
            accf[j] = fmaf(a0, hp[j], fmaf(a1, hc[j], accf[j]));
            accg[j] = fmaf(g0, hp[j], fmaf(g1, hc[j], accg[j]));
        }
    }

    // ---- gating, write gated transposed
    #pragma unroll
    for (int j = 0; j < PPW; j++) {
        float t = tanhf(accf[j]);
        float s = 1.f / (1.f + __expf(-accg[j]));
        gT[o][pb + j] = t * s;
    }
    __syncwarp();   // gated tile for this warp's positions is warp-local

    // ---- skip = W1 @ gated + b1
    float accs[PPW];
    #pragma unroll
    for (int j = 0; j < PPW; j++) accs[j] = b1s[o];
    #pragma unroll 4
    for (int c = 0; c < 32; c++) {
        float wc = w1s[c][o];
        float4 ga = *(const float4*)&gT[c][pb];
        float4 gb = *(const float4*)&gT[c][pb + 4];
        float gv[8] = {ga.x,ga.y,ga.z,ga.w, gb.x,gb.y,gb.z,gb.w};
        #pragma unroll
        for (int j = 0; j < PPW; j++) accs[j] = fmaf(wc, gv[j], accs[j]);
    }

    // ---- residual + skip accumulation (coalesced: lane = channel)
    #pragma unroll
    for (int j = 0; j < PPW; j++) {
        int gi = base + (pb + j)*CH_ + o;
        float hv = hTc[o][pb + j];
        h_out[gi] = hv + accs[j];
        skip_sum[gi] += accs[j];
    }
}

// ---------------------------------------------------------------------------
// y = relu(Wf @ relu(skip_sum) + bf); AdaptiveMaxPool1d(4) -> g_pool[b][c*4+q]
// ---------------------------------------------------------------------------
__global__ __launch_bounds__(NTHR) void pool_kernel(
    const float* __restrict__ skip_sum, const float* __restrict__ Wf,
    const float* __restrict__ bf, float* __restrict__ pool)
{
    __shared__ float wfT[32][32];     // [c][o] = Wf[o][c]
    __shared__ float bfs[32];
    __shared__ float pmax[8][32];
    const int tid = threadIdx.x;
    const int q = blockIdx.x, b = blockIdx.y;

    for (int i = tid; i < 1024; i += NTHR) wfT[i & 31][i >> 5] = Wf[i];
    if (tid < 32) bfs[tid] = bf[tid];
    __syncthreads();

    const int w = tid >> 5, o = tid & 31;
    float m = 0.f;   // relu folded into max (monotone, values clamped at 0)
    for (int p = w; p < L_/4; p += 8) {
        int l = q * (L_/4) + p;
        float sv = fmaxf(skip_sum[(b*L_ + l)*CH_ + o], 0.f);
        float acc = bfs[o];
        #pragma unroll
        for (int c = 0; c < 32; c++)
            acc = fmaf(wfT[c][o], __shfl_sync(0xffffffffu, sv, c), acc);
        m = fmaxf(m, acc);
    }
    pmax[w][o] = m;
    __syncthreads();
    if (w == 0) {
        float mm = pmax[0][o];
        #pragma unroll
        for (int k = 1; k < 8; k++) mm = fmaxf(mm, pmax[k][o]);
        pool[b*128 + o*4 + q] = mm;   // flatten order: k = c*4 + q
    }
}

// ---------------------------------------------------------------------------
// FC head: 128 -> 64 (relu) -> 10
// ---------------------------------------------------------------------------
__global__ void fc_kernel(const float* __restrict__ pool,
                          const float* __restrict__ fW1, const float* __restrict__ fb1,
                          const float* __restrict__ fW2, const float* __restrict__ fb2,
                          float* __restrict__ out)
{
    __shared__ float ps[128], h1[64];
    const int b = blockIdx.x, tid = threadIdx.x;
    ps[tid]      = pool[b*128 + tid];
    ps[tid + 64] = pool[b*128 + 64 + tid];
    __syncthreads();
    float acc = fb1[tid];
    #pragma unroll 8
    for (int k = 0; k < 128; k++) acc = fmaf(fW1[tid*128 + k], ps[k], acc);
    h1[tid] = fmaxf(acc, 0.f);
    __syncthreads();
    if (tid < 10) {
        float a2 = fb2[tid];
        #pragma unroll 8
        for (int k = 0; k < 64; k++) a2 = fmaf(fW2[tid*64 + k], h1[k], a2);
        out[b*10 + tid] = a2;
    }
}

// ---------------------------------------------------------------------------
extern "C" void kernel_launch(void* const* d_in, const int* in_sizes, int n_in,
                              void* d_out, int out_size)
{
    const float* x   = (const float*)d_in[0];
    const float* W0  = (const float*)d_in[1];
    const float* b0  = (const float*)d_in[2];
    const float* Wd  = (const float*)d_in[3];   // (24, 64, 32, 2)
    const float* bd  = (const float*)d_in[4];   // (24, 64)
    const float* W1  = (const float*)d_in[5];   // (24, 32, 32)
    const float* b1  = (const float*)d_in[6];   // (24, 32)
    const float* Wf  = (const float*)d_in[7];
    const float* bf  = (const float*)d_in[8];
    const float* fW1 = (const float*)d_in[9];
    const float* fb1 = (const float*)d_in[10];
    const float* fW2 = (const float*)d_in[11];
    const float* fb2 = (const float*)d_in[12];
    float* out = (float*)d_out;

    float *h0, *h1, *sk, *pl;
    cudaGetSymbolAddress((void**)&h0, g_h0);
    cudaGetSymbolAddress((void**)&h1, g_h1);
    cudaGetSymbolAddress((void**)&sk, g_skip);
    cudaGetSymbolAddress((void**)&pl, g_pool);

    init_kernel<<<(B_*L_*CH_ + 255)/256, 256>>>(x, W0, b0);

    dim3 grid(L_/TILE, B_);
    float* hin = h0;
    float* hout = h1;
    for (int i = 0; i < NBLK; i++) {
        int dil = 1 << (i & 7);
        layer_kernel<<<grid, NTHR>>>(hin, hout, sk,
            Wd + i*64*32*2, bd + i*64, W1 + i*1024, b1 + i*32, dil);
        float* t = hin; hin = hout; hout = t;
    }

    pool_kernel<<<dim3(4, B_), NTHR>>>(sk, Wf, bf, pl);
    fc_kernel<<<B_, 64>>>(pl, fW1, fb1, fW2, fb2, out);
}

// round 5
// speedup vs baseline: 1.9557x; 1.9557x over previous
#include <cuda_runtime.h>

#define B_    16
#define L_    8192
#define CH_   32
#define NBLK  24
#define TILE  64
#define PSTR  68      // row stride: 16B-aligned rows; stride ≡ 4 (mod 32) -> LDS.128
                      // down a "column of rows" covers all 32 banks (conflict-free)
#define NTHR  256
#define PPW   8

typedef unsigned long long u64;

// Scratch (device globals: allocation-free per harness rules)
__device__ float g_h0[B_*L_*CH_];
__device__ float g_h1[B_*L_*CH_];
__device__ float g_skip[B_*L_*CH_];
__device__ float g_pp[B_*128*8];     // pool partial maxes
__device__ float g_pool[B_*128];     // (unused slot kept for layout stability)

// ---- packed f32x2 helpers (FFMA2 is PTX-only; ptxas won't auto-fuse) ------
__device__ __forceinline__ u64 pack2(float a, float b) {
    u64 r; asm("mov.b64 %0, {%1,%2};" : "=l"(r) : "f"(a), "f"(b)); return r;
}
__device__ __forceinline__ void unpack2(u64 v, float& a, float& b) {
    asm("mov.b64 {%0,%1}, %2;" : "=f"(a), "=f"(b) : "l"(v));
}
__device__ __forceinline__ void fma2(u64& d, u64 a, u64 b) {
    asm("fma.rn.f32x2 %0, %1, %2, %0;" : "+l"(d) : "l"(a), "l"(b));
}

// ---------------------------------------------------------------------------
// Initial causal conv (K=2, dil=1): x (B,L) -> h (B,L,32); zero skip_sum.
// ---------------------------------------------------------------------------
__global__ void init_kernel(const float* __restrict__ x,
                            const float* __restrict__ W0,
                            const float* __restrict__ b0) {
    int idx = blockIdx.x * blockDim.x + threadIdx.x;
    if (idx >= B_*L_*CH_) return;
    int c = idx & 31;
    int l = (idx >> 5) & (L_ - 1);
    int b = idx >> 18;
    float xv = x[b*L_ + l];
    float xp = (l > 0) ? x[b*L_ + l - 1] : 0.f;
    g_h0[idx] = fmaf(W0[c*2 + 0], xp, fmaf(W0[c*2 + 1], xv, b0[c]));
    g_skip[idx] = 0.f;
}

// ---------------------------------------------------------------------------
// One WaveNet residual block (f32x2 packed math, conflict-free shared layout)
// ---------------------------------------------------------------------------
__global__ __launch_bounds__(NTHR, 4) void layer_kernel(
    const float* __restrict__ h_in, float* __restrict__ h_out,
    float* __restrict__ skip_sum,
    const float* __restrict__ Wd, const float* __restrict__ bd,
    const float* __restrict__ W1, const float* __restrict__ b1,
    int dil)
{
    // weights: float2 = (tap0, tap1); 33-stride rows -> conflict-free rd/wr
    __shared__ float2 wfp[32][33], wgp[32][33];          // [c][o]
    __shared__ float  w1s[32][33];                       // [c][o] = W1[o][c]
    __shared__ float  bdf[32], bdg[32], b1s[32];
    __shared__ __align__(16) float hTc[32][PSTR];        // [c][pos]
    __shared__ __align__(16) float hTp[32][PSTR];
    __shared__ __align__(16) float gT [32][PSTR];

    const int tid = threadIdx.x;
    const int b  = blockIdx.y;
    const int l0 = blockIdx.x * TILE;
    const int base = (b*L_ + l0) * CH_;

    // ---- stage weights: Wd is [o][c][taps=2] -> read as float2
    const float2* Wd2 = (const float2*)Wd;
    #pragma unroll
    for (int i = tid; i < 2048; i += NTHR) {
        float2 v = Wd2[i];
        int o = i >> 5, c = i & 31;
        if (o < 32) wfp[c][o] = v; else wgp[c][o - 32] = v;
    }
    #pragma unroll
    for (int i = tid; i < 1024; i += NTHR)
        w1s[i & 31][i >> 5] = W1[i];
    if (tid < 32) { bdf[tid] = bd[tid]; bdg[tid] = bd[32 + tid]; b1s[tid] = b1[tid]; }

    // ---- stage h tiles transposed; 4 positions per thread, STS.128
    const float* hb = h_in + b*L_*CH_;
    #pragma unroll
    for (int i = tid; i < 512; i += NTHR) {
        int c = i & 31, lq = (i >> 5) << 2;
        float4 vc;
        int gi = base + lq*CH_ + c;
        vc.x = h_in[gi]; vc.y = h_in[gi+32]; vc.z = h_in[gi+64]; vc.w = h_in[gi+96];
        *(float4*)&hTc[c][lq] = vc;
        int lp = l0 + lq - dil;
        float4 vp;
        vp.x = (lp   >= 0) ? hb[(lp  )*CH_ + c] : 0.f;
        vp.y = (lp+1 >= 0) ? hb[(lp+1)*CH_ + c] : 0.f;
        vp.z = (lp+2 >= 0) ? hb[(lp+2)*CH_ + c] : 0.f;
        vp.w = (lp+3 >= 0) ? hb[(lp+3)*CH_ + c] : 0.f;
        *(float4*)&hTp[c][lq] = vp;
    }
    __syncthreads();

    const int w  = tid >> 5;
    const int o  = tid & 31;
    const int pb = w * PPW;

    // ---- dilated conv: 64 outputs (f,g) over 8 positions, packed pairs
    u64 af[4], ag[4];
    {
        u64 bf2 = pack2(bdf[o], bdf[o]);
        u64 bg2 = pack2(bdg[o], bdg[o]);
        #pragma unroll
        for (int p = 0; p < 4; p++) { af[p] = bf2; ag[p] = bg2; }
    }
    #pragma unroll 8
    for (int c = 0; c < 32; c++) {
        float2 wf = wfp[c][o], wg = wgp[c][o];
        u64 a0 = pack2(wf.x, wf.x), a1 = pack2(wf.y, wf.y);
        u64 q0 = pack2(wg.x, wg.x), q1 = pack2(wg.y, wg.y);
        ulonglong2 hp0 = *(const ulonglong2*)&hTp[c][pb];
        ulonglong2 hp1 = *(const ulonglong2*)&hTp[c][pb + 4];
        ulonglong2 hc0 = *(const ulonglong2*)&hTc[c][pb];
        ulonglong2 hc1 = *(const ulonglong2*)&hTc[c][pb + 4];
        fma2(af[0], a0, hp0.x); fma2(af[0], a1, hc0.x);
        fma2(af[1], a0, hp0.y); fma2(af[1], a1, hc0.y);
        fma2(af[2], a0, hp1.x); fma2(af[2], a1, hc1.x);
        fma2(af[3], a0, hp1.y); fma2(af[3], a1, hc1.y);
        fma2(ag[0], q0, hp0.x); fma2(ag[0], q1, hc0.x);
        fma2(ag[1], q0, hp0.y); fma2(ag[1], q1, hc0.y);
        fma2(ag[2], q0, hp1.x); fma2(ag[2], q1, hc1.x);
        fma2(ag[3], q0, hp1.y); fma2(ag[3], q1, hc1.y);
    }

    // ---- gating: tanh(f)*sigmoid(g) via MUFU (ex2 + rcp); write gT (STS.128)
    float gv[8];
    #pragma unroll
    for (int p = 0; p < 4; p++) {
        float f0, f1, g0, g1;
        unpack2(af[p], f0, f1);
        unpack2(ag[p], g0, g1);
        float t0 = 1.f - __fdividef(2.f, __expf(2.f*f0) + 1.f);
        float t1 = 1.f - __fdividef(2.f, __expf(2.f*f1) + 1.f);
        float s0 = __fdividef(1.f, 1.f + __expf(-g0));
        float s1 = __fdividef(1.f, 1.f + __expf(-g1));
        gv[2*p]   = t0 * s0;
        gv[2*p+1] = t1 * s1;
    }
    *(float4*)&gT[o][pb]     = make_float4(gv[0], gv[1], gv[2], gv[3]);
    *(float4*)&gT[o][pb + 4] = make_float4(gv[4], gv[5], gv[6], gv[7]);
    __syncwarp();   // gated tile for this warp's positions is warp-local

    // ---- skip = W1 @ gated + b1 (packed)
    u64 as[4];
    {
        u64 bs2 = pack2(b1s[o], b1s[o]);
        #pragma unroll
        for (int p = 0; p < 4; p++) as[p] = bs2;
    }
    #pragma unroll 8
    for (int c = 0; c < 32; c++) {
        float wv = w1s[c][o];
        u64 wd = pack2(wv, wv);
        ulonglong2 gg0 = *(const ulonglong2*)&gT[c][pb];
        ulonglong2 gg1 = *(const ulonglong2*)&gT[c][pb + 4];
        fma2(as[0], wd, gg0.x); fma2(as[1], wd, gg0.y);
        fma2(as[2], wd, gg1.x); fma2(as[3], wd, gg1.y);
    }

    // ---- residual + skip accumulation
    float4 hv0 = *(const float4*)&hTc[o][pb];
    float4 hv1 = *(const float4*)&hTc[o][pb + 4];
    float hv[8] = {hv0.x,hv0.y,hv0.z,hv0.w, hv1.x,hv1.y,hv1.z,hv1.w};
    float sk[8];
    #pragma unroll
    for (int p = 0; p < 4; p++) unpack2(as[p], sk[2*p], sk[2*p+1]);
    #pragma unroll
    for (int j = 0; j < PPW; j++) {
        int gi = base + (pb + j)*CH_ + o;
        h_out[gi]  = hv[j] + sk[j];
        skip_sum[gi] += sk[j];
    }
}

// ---------------------------------------------------------------------------
// pool: y = relu(Wf@relu(skip)+bf) max-pooled; 8-way split over L for
// parallelism; partial maxes -> g_pp, reduced in fc_kernel.
// ---------------------------------------------------------------------------
__global__ __launch_bounds__(NTHR) void pool_kernel(
    const float* __restrict__ skip_sum, const float* __restrict__ Wf,
    const float* __restrict__ bf, float* __restrict__ pp)
{
    __shared__ float wfT[32][33];
    __shared__ float bfs[32];
    __shared__ float pmax[8][32];
    const int tid = threadIdx.x;
    const int q = blockIdx.x >> 3, s = blockIdx.x & 7;
    const int b = blockIdx.y;

    for (int i = tid; i < 1024; i += NTHR) wfT[i & 31][i >> 5] = Wf[i];
    if (tid < 32) bfs[tid] = bf[tid];
    __syncthreads();

    const int w = tid >> 5, o = tid & 31;
    const int lbase = q * (L_/4) + s * (L_/32);
    float m = 0.f;   // relu folded into max
    for (int p = w; p < L_/32; p += 8) {
        int l = lbase + p;
        float sv = fmaxf(skip_sum[(b*L_ + l)*CH_ + o], 0.f);
        float acc = bfs[o];
        #pragma unroll
        for (int c = 0; c < 32; c++)
            acc = fmaf(wfT[c][o], __shfl_sync(0xffffffffu, sv, c), acc);
        m = fmaxf(m, acc);
    }
    pmax[w][o] = m;
    __syncthreads();
    if (w == 0) {
        float mm = pmax[0][o];
        #pragma unroll
        for (int k = 1; k < 8; k++) mm = fmaxf(mm, pmax[k][o]);
        pp[b*1024 + (o*4 + q)*8 + s] = mm;   // feature index = c*4 + q
    }
}

// ---------------------------------------------------------------------------
// FC head: reduce partials, 128 -> 64 (relu) -> 10
// ---------------------------------------------------------------------------
__global__ void fc_kernel(const float* __restrict__ pp,
                          const float* __restrict__ fW1, const float* __restrict__ fb1,
                          const float* __restrict__ fW2, const float* __restrict__ fb2,
                          float* __restrict__ out)
{
    __shared__ float ps[128], h1[64];
    const int b = blockIdx.x, tid = threadIdx.x;
    #pragma unroll
    for (int f = tid; f < 128; f += 64) {
        const float* p = pp + b*1024 + f*8;
        float m = p[0];
        #pragma unroll
        for (int k = 1; k < 8; k++) m = fmaxf(m, p[k]);
        ps[f] = m;
    }
    __syncthreads();
    float acc = fb1[tid];
    #pragma unroll 8
    for (int k = 0; k < 128; k++) acc = fmaf(fW1[tid*128 + k], ps[k], acc);
    h1[tid] = fmaxf(acc, 0.f);
    __syncthreads();
    if (tid < 10) {
        float a2 = fb2[tid];
        #pragma unroll 8
        for (int k = 0; k < 64; k++) a2 = fmaf(fW2[tid*64 + k], h1[k], a2);
        out[b*10 + tid] = a2;
    }
}

// ---------------------------------------------------------------------------
extern "C" void kernel_launch(void* const* d_in, const int* in_sizes, int n_in,
                              void* d_out, int out_size)
{
    const float* x   = (const float*)d_in[0];
    const float* W0  = (const float*)d_in[1];
    const float* b0  = (const float*)d_in[2];
    const float* Wd  = (const float*)d_in[3];   // (24, 64, 32, 2)
    const float* bd  = (const float*)d_in[4];   // (24, 64)
    const float* W1  = (const float*)d_in[5];   // (24, 32, 32)
    const float* b1  = (const float*)d_in[6];   // (24, 32)
    const float* Wf  = (const float*)d_in[7];
    const float* bf  = (const float*)d_in[8];
    const float* fW1 = (const float*)d_in[9];
    const float* fb1 = (const float*)d_in[10];
    const float* fW2 = (const float*)d_in[11];
    const float* fb2 = (const float*)d_in[12];
    float* out = (float*)d_out;

    float *h0, *h1, *sk, *pp;
    cudaGetSymbolAddress((void**)&h0, g_h0);
    cudaGetSymbolAddress((void**)&h1, g_h1);
    cudaGetSymbolAddress((void**)&sk, g_skip);
    cudaGetSymbolAddress((void**)&pp, g_pp);

    init_kernel<<<(B_*L_*CH_ + 255)/256, 256>>>(x, W0, b0);

    dim3 grid(L_/TILE, B_);
    float* hin = h0;
    float* hout = h1;
    for (int i = 0; i < NBLK; i++) {
        int dil = 1 << (i & 7);
        layer_kernel<<<grid, NTHR>>>(hin, hout, sk,
            Wd + i*64*32*2, bd + i*64, W1 + i*1024, b1 + i*32, dil);
        float* t = hin; hin = hout; hout = t;
    }

    pool_kernel<<<dim3(32, B_), NTHR>>>(sk, Wf, bf, pp);
    fc_kernel<<<B_, 64>>>(pp, fW1, fb1, fW2, fb2, out);
}

// round 6
// speedup vs baseline: 2.1536x; 1.1012x over previous
#include <cuda_runtime.h>

#define B_    16
#define L_    8192
#define CH_   32
#define NBLK  24
#define TILE  128
#define PSTR  132     // row stride ≡ 4 (mod 32), 16B aligned -> conflict-free .128 column ops
#define NTHR  256
#define PPW   16      // positions per thread; warp = 32 out-channels x 16 positions

typedef unsigned long long u64;

// Scratch (device globals: allocation-free per harness rules)
__device__ float g_hi[B_*L_*CH_];    // init conv output (kept for skip_sum = h_fin - h_init)
__device__ float g_ha[B_*L_*CH_];
__device__ float g_hb[B_*L_*CH_];
__device__ float g_pp[B_*128*8];     // pool partial maxes

// ---- packed f32x2 helpers (FFMA2 is PTX-only; ptxas won't auto-fuse) ------
__device__ __forceinline__ u64 pack2(float a, float b) {
    u64 r; asm("mov.b64 %0, {%1,%2};" : "=l"(r) : "f"(a), "f"(b)); return r;
}
__device__ __forceinline__ void unpack2(u64 v, float& a, float& b) {
    asm("mov.b64 {%0,%1}, %2;" : "=f"(a), "=f"(b) : "l"(v));
}
__device__ __forceinline__ void fma2(u64& d, u64 a, u64 b) {
    asm("fma.rn.f32x2 %0, %1, %2, %0;" : "+l"(d) : "l"(a), "l"(b));
}

struct __align__(16) Smem {
    float2 wfp[32][33];                 // [c][o] = (tap0, tap1) of f-half
    float2 wgp[32][33];                 // [c][o] = (tap0, tap1) of g-half
    float  w1s[32][33];                 // [c][o] = W1[o][c]
    float  bdf[32], bdg[32], b1s[32];
    float  hTc[32][PSTR];               // [c][pos]
    float  hTp[32][PSTR];
    float  gT [32][PSTR];
};
#define SMEM_BYTES ((int)sizeof(Smem))

// ---------------------------------------------------------------------------
// Initial causal conv (K=2, dil=1): x (B,L) -> h_init (B,L,32)
// ---------------------------------------------------------------------------
__global__ void init_kernel(const float* __restrict__ x,
                            const float* __restrict__ W0,
                            const float* __restrict__ b0) {
    int idx = blockIdx.x * blockDim.x + threadIdx.x;
    if (idx >= B_*L_*CH_) return;
    int c = idx & 31;
    int l = (idx >> 5) & (L_ - 1);
    int b = idx >> 18;
    float xv = x[b*L_ + l];
    float xp = (l > 0) ? x[b*L_ + l - 1] : 0.f;
    g_hi[idx] = fmaf(W0[c*2 + 0], xp, fmaf(W0[c*2 + 1], xv, b0[c]));
}

// ---------------------------------------------------------------------------
// One WaveNet residual block: h_out = h_in + W1@(tanh(f)*sigmoid(g)) + b1
// (skip_sum is implicit: recovered later as h_final - h_init)
// ---------------------------------------------------------------------------
__global__ void __launch_bounds__(NTHR, 2) layer_kernel(
    const float* __restrict__ h_in, float* __restrict__ h_out,
    const float* __restrict__ Wd, const float* __restrict__ bd,
    const float* __restrict__ W1, const float* __restrict__ b1,
    int dil)
{
    extern __shared__ char smem_raw[];
    Smem& S = *reinterpret_cast<Smem*>(smem_raw);

    const int tid = threadIdx.x;
    const int b  = blockIdx.y;
    const int l0 = blockIdx.x * TILE;
    const int base = (b*L_ + l0) * CH_;

    // ---- stage weights: Wd is [o][c][taps=2] -> read as float2
    const float2* Wd2 = (const float2*)Wd;
    #pragma unroll
    for (int i = tid; i < 2048; i += NTHR) {
        float2 v = Wd2[i];
        int o = i >> 5, c = i & 31;
        if (o < 32) S.wfp[c][o] = v; else S.wgp[c][o - 32] = v;
    }
    #pragma unroll
    for (int i = tid; i < 1024; i += NTHR)
        S.w1s[i & 31][i >> 5] = W1[i];
    if (tid < 32) { S.bdf[tid] = bd[tid]; S.bdg[tid] = bd[32 + tid]; S.b1s[tid] = b1[tid]; }

    // ---- stage h tiles transposed to [c][pos]; 4 positions per iter, STS.128
    const float* hb = h_in + b*L_*CH_;
    #pragma unroll
    for (int i = tid; i < 1024; i += NTHR) {
        int c = i & 31, lq = (i >> 5) << 2;
        int gi = base + lq*CH_ + c;
        float4 vc;
        vc.x = h_in[gi]; vc.y = h_in[gi+32]; vc.z = h_in[gi+64]; vc.w = h_in[gi+96];
        *(float4*)&S.hTc[c][lq] = vc;
        int lp = l0 + lq - dil;
        float4 vp;
        vp.x = (lp   >= 0) ? hb[(lp  )*CH_ + c] : 0.f;
        vp.y = (lp+1 >= 0) ? hb[(lp+1)*CH_ + c] : 0.f;
        vp.z = (lp+2 >= 0) ? hb[(lp+2)*CH_ + c] : 0.f;
        vp.w = (lp+3 >= 0) ? hb[(lp+3)*CH_ + c] : 0.f;
        *(float4*)&S.hTp[c][lq] = vp;
    }
    __syncthreads();

    const int w  = tid >> 5;       // warp -> 16-position group
    const int o  = tid & 31;       // lane -> output channel
    const int pb = w * PPW;

    // ---- dilated conv: (f,g) outputs over 16 positions, packed position-pairs
    u64 af[8], ag[8];
    {
        u64 bf2 = pack2(S.bdf[o], S.bdf[o]);
        u64 bg2 = pack2(S.bdg[o], S.bdg[o]);
        #pragma unroll
        for (int p = 0; p < 8; p++) { af[p] = bf2; ag[p] = bg2; }
    }
    #pragma unroll 8
    for (int c = 0; c < 32; c++) {
        float2 wf = S.wfp[c][o], wg = S.wgp[c][o];
        u64 a0 = pack2(wf.x, wf.x), a1 = pack2(wf.y, wf.y);
        u64 q0 = pack2(wg.x, wg.x), q1 = pack2(wg.y, wg.y);
        #pragma unroll
        for (int q = 0; q < 4; q++) {
            ulonglong2 hp = *(const ulonglong2*)&S.hTp[c][pb + 4*q];
            ulonglong2 hc = *(const ulonglong2*)&S.hTc[c][pb + 4*q];
            fma2(af[2*q],   a0, hp.x); fma2(af[2*q],   a1, hc.x);
            fma2(af[2*q+1], a0, hp.y); fma2(af[2*q+1], a1, hc.y);
            fma2(ag[2*q],   q0, hp.x); fma2(ag[2*q],   q1, hc.x);
            fma2(ag[2*q+1], q0, hp.y); fma2(ag[2*q+1], q1, hc.y);
        }
    }

    // ---- gating: tanh(f)*sigmoid(g) via __expf; write gT (STS.128)
    float gv[16];
    #pragma unroll
    for (int p = 0; p < 8; p++) {
        float f0, f1, g0, g1;
        unpack2(af[p], f0, f1);
        unpack2(ag[p], g0, g1);
        float t0 = 1.f - __fdividef(2.f, __expf(2.f*f0) + 1.f);
        float t1 = 1.f - __fdividef(2.f, __expf(2.f*f1) + 1.f);
        float s0 = __fdividef(1.f, 1.f + __expf(-g0));
        float s1 = __fdividef(1.f, 1.f + __expf(-g1));
        gv[2*p]   = t0 * s0;
        gv[2*p+1] = t1 * s1;
    }
    #pragma unroll
    for (int q = 0; q < 4; q++)
        *(float4*)&S.gT[o][pb + 4*q] = make_float4(gv[4*q], gv[4*q+1], gv[4*q+2], gv[4*q+3]);
    __syncwarp();   // gated tile for this warp's position range is warp-local

    // ---- skip = W1 @ gated + b1 (packed)
    u64 as[8];
    {
        u64 bs2 = pack2(S.b1s[o], S.b1s[o]);
        #pragma unroll
        for (int p = 0; p < 8; p++) as[p] = bs2;
    }
    #pragma unroll 8
    for (int c = 0; c < 32; c++) {
        float wv = S.w1s[c][o];
        u64 wd = pack2(wv, wv);
        #pragma unroll
        for (int q = 0; q < 4; q++) {
            ulonglong2 gg = *(const ulonglong2*)&S.gT[c][pb + 4*q];
            fma2(as[2*q], wd, gg.x); fma2(as[2*q+1], wd, gg.y);
        }
    }

    // ---- residual: h_out = h_in + skip (coalesced: lane = channel)
    float sk[16];
    #pragma unroll
    for (int p = 0; p < 8; p++) unpack2(as[p], sk[2*p], sk[2*p+1]);
    #pragma unroll
    for (int q = 0; q < 4; q++) {
        float4 hv = *(const float4*)&S.hTc[o][pb + 4*q];
        int gi = base + (pb + 4*q)*CH_ + o;
        h_out[gi]      = hv.x + sk[4*q];
        h_out[gi + 32] = hv.y + sk[4*q+1];
        h_out[gi + 64] = hv.z + sk[4*q+2];
        h_out[gi + 96] = hv.w + sk[4*q+3];
    }
}

// ---------------------------------------------------------------------------
// pool: skip_sum = h_fin - h_init; y = relu(Wf@relu(skip)+bf) max-pooled.
// 8-way split over L; partial maxes -> g_pp, reduced in fc_kernel.
// ---------------------------------------------------------------------------
__global__ __launch_bounds__(NTHR) void pool_kernel(
    const float* __restrict__ h_fin, const float* __restrict__ h_init,
    const float* __restrict__ Wf, const float* __restrict__ bf,
    float* __restrict__ pp)
{
    __shared__ float wfT[32][33];
    __shared__ float bfs[32];
    __shared__ float pmax[8][32];
    const int tid = threadIdx.x;
    const int q = blockIdx.x >> 3, s = blockIdx.x & 7;
    const int b = blockIdx.y;

    for (int i = tid; i < 1024; i += NTHR) wfT[i & 31][i >> 5] = Wf[i];
    if (tid < 32) bfs[tid] = bf[tid];
    __syncthreads();

    const int w = tid >> 5, o = tid & 31;
    const int lbase = q * (L_/4) + s * (L_/32);
    float m = 0.f;   // relu folded into max
    for (int p = w; p < L_/32; p += 8) {
        int gi = (b*L_ + lbase + p)*CH_ + o;
        float sv = fmaxf(h_fin[gi] - h_init[gi], 0.f);
        float acc = bfs[o];
        #pragma unroll
        for (int c = 0; c < 32; c++)
            acc = fmaf(wfT[c][o], __shfl_sync(0xffffffffu, sv, c), acc);
        m = fmaxf(m, acc);
    }
    pmax[w][o] = m;
    __syncthreads();
    if (w == 0) {
        float mm = pmax[0][o];
        #pragma unroll
        for (int k = 1; k < 8; k++) mm = fmaxf(mm, pmax[k][o]);
        pp[b*1024 + (o*4 + q)*8 + s] = mm;   // feature index = c*4 + q
    }
}

// ---------------------------------------------------------------------------
// FC head: reduce partials, 128 -> 64 (relu) -> 10
// ---------------------------------------------------------------------------
__global__ void fc_kernel(const float* __restrict__ pp,
                          const float* __restrict__ fW1, const float* __restrict__ fb1,
                          const float* __restrict__ fW2, const float* __restrict__ fb2,
                          float* __restrict__ out)
{
    __shared__ float ps[128], h1[64];
    const int b = blockIdx.x, tid = threadIdx.x;
    #pragma unroll
    for (int f = tid; f < 128; f += 64) {
        const float* p = pp + b*1024 + f*8;
        float m = p[0];
        #pragma unroll
        for (int k = 1; k < 8; k++) m = fmaxf(m, p[k]);
        ps[f] = m;
    }
    __syncthreads();
    float acc = fb1[tid];
    #pragma unroll 8
    for (int k = 0; k < 128; k++) acc = fmaf(fW1[tid*128 + k], ps[k], acc);
    h1[tid] = fmaxf(acc, 0.f);
    __syncthreads();
    if (tid < 10) {
        float a2 = fb2[tid];
        #pragma unroll 8
        for (int k = 0; k < 64; k++) a2 = fmaf(fW2[tid*64 + k], h1[k], a2);
        out[b*10 + tid] = a2;
    }
}

// ---------------------------------------------------------------------------
extern "C" void kernel_launch(void* const* d_in, const int* in_sizes, int n_in,
                              void* d_out, int out_size)
{
    const float* x   = (const float*)d_in[0];
    const float* W0  = (const float*)d_in[1];
    const float* b0  = (const float*)d_in[2];
    const float* Wd  = (const float*)d_in[3];   // (24, 64, 32, 2)
    const float* bd  = (const float*)d_in[4];   // (24, 64)
    const float* W1  = (const float*)d_in[5];   // (24, 32, 32)
    const float* b1  = (const float*)d_in[6];   // (24, 32)
    const float* Wf  = (const float*)d_in[7];
    const float* bf  = (const float*)d_in[8];
    const float* fW1 = (const float*)d_in[9];
    const float* fb1 = (const float*)d_in[10];
    const float* fW2 = (const float*)d_in[11];
    const float* fb2 = (const float*)d_in[12];
    float* out = (float*)d_out;

    static bool attr_done = false;
    if (!attr_done) {
        cudaFuncSetAttribute(layer_kernel,
            cudaFuncAttributeMaxDynamicSharedMemorySize, SMEM_BYTES);
        attr_done = true;
    }

    float *hi, *ha, *hbuf, *pp;
    cudaGetSymbolAddress((void**)&hi,   g_hi);
    cudaGetSymbolAddress((void**)&ha,   g_ha);
    cudaGetSymbolAddress((void**)&hbuf, g_hb);
    cudaGetSymbolAddress((void**)&pp,   g_pp);

    init_kernel<<<(B_*L_*CH_ + 255)/256, 256>>>(x, W0, b0);

    dim3 grid(L_/TILE, B_);
    const float* hin = hi;
    for (int i = 0; i < NBLK; i++) {
        int dil = 1 << (i & 7);
        float* hout = (i & 1) ? hbuf : ha;
        layer_kernel<<<grid, NTHR, SMEM_BYTES>>>(hin, hout,
            Wd + i*64*32*2, bd + i*64, W1 + i*1024, b1 + i*32, dil);
        hin = hout;
    }
    // NBLK=24 even -> final h is in g_hb (written at odd i, last i=23)

    pool_kernel<<<dim3(32, B_), NTHR>>>(hbuf, hi, Wf, bf, pp);
    fc_kernel<<<B_, 64>>>(pp, fW1, fb1, fW2, fb2, out);
}